// round 10
// baseline (speedup 1.0000x reference)
#include <cuda_runtime.h>
#include <cstdint>

#define NN 100000
#define NE 800000
#define LDA 36
#define LDH 132
#define CSR_BLOCKS 196
#define CSR_THREADS 512

// ---------------- device scratch ----------------
__device__ float g_mean[(size_t)NN * 128];   // mean-aggregated x
__device__ float g_t2  [(size_t)NN * 40];    // h @ W2l
__device__ float g_r2  [(size_t)NN * 40];    // h @ W2r
__device__ int   g_icnt[NN];
__device__ float g_inv [NN];
__device__ int   g_rowptr[NN];
__device__ int   g_cursor[NN];
__device__ int   g_adj [NE];
__device__ int   g_src [NE];
__device__ int   g_dst [NE];
__device__ int   g_bsum[CSR_BLOCKS];
__device__ int   g_is64;
__device__ float g_W1t[128 * 256];   // B layer1: [n=128][k=256], tf32-rna
__device__ float g_W2t[80 * 128];    // B layer2: [n=80][k=128], tf32-rna
__device__ unsigned int g_bcount = 0;
__device__ unsigned int g_bsense = 0;

// ---------------- helpers ----------------
__device__ __forceinline__ float f2tf(float f) {
    unsigned int r;
    asm("cvt.rna.tf32.f32 %0, %1;" : "=r"(r) : "f"(f));
    return __uint_as_float(r);
}
__device__ __forceinline__ void cp16(uint32_t dst, const void* src) {
    asm volatile("cp.async.cg.shared.global [%0], [%1], 16;" :: "r"(dst), "l"(src));
}
__device__ __forceinline__ void mma8(float* c, float a0, float a1, float a2, float a3,
                                     float b0, float b1) {
    asm volatile("mma.sync.aligned.m16n8k8.row.col.f32.tf32.tf32.f32 "
        "{%0,%1,%2,%3}, {%4,%5,%6,%7}, {%8,%9}, {%0,%1,%2,%3};"
        : "+f"(c[0]), "+f"(c[1]), "+f"(c[2]), "+f"(c[3])
        : "r"(__float_as_uint(a0)), "r"(__float_as_uint(a1)),
          "r"(__float_as_uint(a2)), "r"(__float_as_uint(a3)),
          "r"(__float_as_uint(b0)), "r"(__float_as_uint(b1)));
}

// sense-reversal grid barrier; re-entrant across launches (count returns to 0,
// sense compared by equality). Safe: grid (196 x 512thr) fully resident on 148 SMs.
__device__ __forceinline__ void grid_sync() {
    __syncthreads();
    if (threadIdx.x == 0) {
        __threadfence();
        unsigned int seen = atomicAdd(&g_bsense, 0u);
        unsigned int my = atomicAdd(&g_bcount, 1u);
        if (my == (unsigned)gridDim.x - 1u) {
            g_bcount = 0;
            __threadfence();
            atomicAdd(&g_bsense, 1u);
        } else {
            while (atomicAdd(&g_bsense, 0u) == seen) {}
        }
        __threadfence();
    }
    __syncthreads();
}

// ---------------- fused CSR build (5 phases, 4 grid barriers) ----------------
__global__ void __launch_bounds__(CSR_THREADS) build_csr(
        const unsigned int* __restrict__ w, const void* __restrict__ ei,
        const float* __restrict__ W1l, const float* __restrict__ W1r,
        const float* __restrict__ W2l, const float* __restrict__ W2r) {
    __shared__ int sb[CSR_THREADS];
    __shared__ int sh[CSR_THREADS];
    const int t = threadIdx.x;
    const int gid = blockIdx.x * CSR_THREADS + t;      // 0..100351
    const int NT = CSR_BLOCKS * CSR_THREADS;           // 100352

    // phase 0: zero degree counts; block 0 detects edge dtype; prep weights
    if (gid < NN) g_icnt[gid] = 0;
    if (blockIdx.x == 0) {
        int nz = 0;
        for (int q = t; q < 2048; q += CSR_THREADS)
            nz |= (w[2 * q + 1] != 0u);
        nz = __syncthreads_or(nz);
        if (t == 0) g_is64 = (nz == 0) ? 1 : 0;
    }
    if (gid < 32768) {
        int k = gid >> 7, n = gid & 127;
        float v = (k < 128) ? W1l[k * 128 + n] : W1r[(k - 128) * 128 + n];
        g_W1t[n * 256 + k] = f2tf(v);
    } else if (gid < 32768 + 10240) {
        int u = gid - 32768;
        int k = u / 80, n = u - k * 80;
        float v = (n < 40) ? W2l[k * 40 + n] : W2r[k * 40 + (n - 40)];
        g_W2t[n * 128 + k] = f2tf(v);
    }
    grid_sync();

    // phase 1: convert edges + count degrees
    {
        const int is64 = g_is64;
        for (int j = gid; j < NE; j += NT) {
            int s, d;
            if (is64) {
                const long long* p = (const long long*)ei;
                s = (int)p[j]; d = (int)p[NE + j];
            } else {
                const int* p = (const int*)ei;
                s = p[j]; d = p[NE + j];
            }
            g_src[j] = s;
            g_dst[j] = d;
            atomicAdd(&g_icnt[d], 1);
        }
    }
    grid_sync();

    // phase 2: per-block degree sums (196 segments of 512 nodes)
    {
        int i = blockIdx.x * CSR_THREADS + t;
        sh[t] = (i < NN) ? g_icnt[i] : 0;
        #pragma unroll
        for (int o = 256; o > 0; o >>= 1) {
            __syncthreads();
            if (t < o) sh[t] += sh[t + o];
        }
        if (t == 0) g_bsum[blockIdx.x] = sh[0];
    }
    grid_sync();

    // phase 3: scan block sums (redundantly per block) + local scan -> rowptr/cursor/inv
    {
        sb[t] = (t < CSR_BLOCKS) ? g_bsum[t] : 0;
        __syncthreads();
        #pragma unroll
        for (int o = 1; o < CSR_THREADS; o <<= 1) {
            int v = (t >= o) ? sb[t - o] : 0;
            __syncthreads();
            sb[t] += v;
            __syncthreads();
        }
        int blockoff = blockIdx.x ? sb[blockIdx.x - 1] : 0;

        int i = blockIdx.x * CSR_THREADS + t;
        int v = (i < NN) ? g_icnt[i] : 0;
        sh[t] = v;
        __syncthreads();
        #pragma unroll
        for (int o = 1; o < CSR_THREADS; o <<= 1) {
            int u = (t >= o) ? sh[t - o] : 0;
            __syncthreads();
            sh[t] += u;
            __syncthreads();
        }
        if (i < NN) {
            int excl = blockoff + sh[t] - v;
            g_rowptr[i] = excl;
            g_cursor[i] = excl;
            g_inv[i] = 1.0f / fmaxf((float)v, 1.0f);
        }
    }
    grid_sync();

    // phase 4: fill adjacency
    for (int j = gid; j < NE; j += NT) {
        int slot = atomicAdd(&g_cursor[g_dst[j]], 1);
        g_adj[slot] = g_src[j];
    }
}

// ---------------- gather layer 1 ----------------
__global__ void __launch_bounds__(256) gather1_kernel(const float* __restrict__ x) {
    int node = (blockIdx.x * blockDim.x + threadIdx.x) >> 5;
    int lane = threadIdx.x & 31;
    if (node >= NN) return;
    int beg = g_rowptr[node];
    int end = beg + g_icnt[node];
    const float4* x4 = (const float4*)x;
    float4 acc = {0.f, 0.f, 0.f, 0.f};
    int j = beg;
    for (; j + 4 <= end; j += 4) {
        int s0 = __ldg(&g_adj[j]);
        int s1 = __ldg(&g_adj[j + 1]);
        int s2 = __ldg(&g_adj[j + 2]);
        int s3 = __ldg(&g_adj[j + 3]);
        float4 v0 = x4[(size_t)s0 * 32 + lane];
        float4 v1 = x4[(size_t)s1 * 32 + lane];
        float4 v2 = x4[(size_t)s2 * 32 + lane];
        float4 v3 = x4[(size_t)s3 * 32 + lane];
        acc.x += (v0.x + v1.x) + (v2.x + v3.x);
        acc.y += (v0.y + v1.y) + (v2.y + v3.y);
        acc.z += (v0.z + v1.z) + (v2.z + v3.z);
        acc.w += (v0.w + v1.w) + (v2.w + v3.w);
    }
    for (; j < end; j++) {
        int s = __ldg(&g_adj[j]);
        float4 v = x4[(size_t)s * 32 + lane];
        acc.x += v.x; acc.y += v.y; acc.z += v.z; acc.w += v.w;
    }
    float iv = g_inv[node];
    acc.x *= iv; acc.y *= iv; acc.z *= iv; acc.w *= iv;
    ((float4*)g_mean)[(size_t)node * 32 + lane] = acc;
}

// ---------------- gather layer 2 + epilogue ----------------
__global__ void __launch_bounds__(320) gather2_kernel(const float* __restrict__ b2,
                                                      float* __restrict__ out) {
    int i = blockIdx.x * blockDim.x + threadIdx.x;
    if (i >= NN * 10) return;
    int node = i / 10;
    int c = i - node * 10;
    int beg = g_rowptr[node];
    int end = beg + g_icnt[node];
    const float4* t4 = (const float4*)g_t2;
    float4 acc = {0.f, 0.f, 0.f, 0.f};
    int j = beg;
    for (; j + 4 <= end; j += 4) {
        int s0 = __ldg(&g_adj[j]);
        int s1 = __ldg(&g_adj[j + 1]);
        int s2 = __ldg(&g_adj[j + 2]);
        int s3 = __ldg(&g_adj[j + 3]);
        float4 v0 = t4[(size_t)s0 * 10 + c];
        float4 v1 = t4[(size_t)s1 * 10 + c];
        float4 v2 = t4[(size_t)s2 * 10 + c];
        float4 v3 = t4[(size_t)s3 * 10 + c];
        acc.x += (v0.x + v1.x) + (v2.x + v3.x);
        acc.y += (v0.y + v1.y) + (v2.y + v3.y);
        acc.z += (v0.z + v1.z) + (v2.z + v3.z);
        acc.w += (v0.w + v1.w) + (v2.w + v3.w);
    }
    for (; j < end; j++) {
        int s = __ldg(&g_adj[j]);
        float4 v = t4[(size_t)s * 10 + c];
        acc.x += v.x; acc.y += v.y; acc.z += v.z; acc.w += v.w;
    }
    float iv = g_inv[node];
    float4 r = ((const float4*)g_r2)[i];
    float4 b = ((const float4*)b2)[c];
    float4 o;
    o.x = acc.x * iv + r.x + b.x;
    o.y = acc.y * iv + r.y + b.y;
    o.z = acc.z * iv + r.z + b.z;
    o.w = acc.w * iv + r.w + b.w;
    ((float4*)out)[i] = o;
}

// ---------------- fused GEMM (R6 config: full SMEM staging, 1 CTA/SM) ----------------
#define SM_A  0
#define SM_B  (2 * 128 * LDA)
#define SM_H  (SM_B + 2 * 128 * LDA)
#define SM_W2 (SM_H + 128 * LDH)
#define SM_BI (SM_W2 + 80 * LDH)
#define GF_SMEM ((SM_BI + 128) * 4)
__global__ void __launch_bounds__(256) gemm_fused(const float* __restrict__ X,
                                                  const float* __restrict__ bias) {
    extern __shared__ float smem[];
    float* sA = smem + SM_A;
    float* sB = smem + SM_B;
    float* sH = smem + SM_H;
    float* sW2 = smem + SM_W2;
    float* sBias = smem + SM_BI;

    const int tid = threadIdx.x, lane = tid & 31, wid = tid >> 5;
    const int wm = wid & 3, wn = wid >> 2;
    const int row0 = blockIdx.x * 128;
    if (tid < 128) sBias[tid] = bias[tid];

    {   // stage W2 [80][128] -> sW2 [80][LDH]
        const float4* src = (const float4*)g_W2t;
        #pragma unroll
        for (int t = 0; t < 10; t++) {
            int i = tid + t * 256;
            int n = i >> 5, kq = i & 31;
            ((float4*)sW2)[n * (LDH / 4) + kq] = src[i];
        }
    }

    float acc[2][8][4];
    #pragma unroll
    for (int mt = 0; mt < 2; mt++)
        #pragma unroll
        for (int nt = 0; nt < 8; nt++)
            #pragma unroll
            for (int q = 0; q < 4; q++) acc[mt][nt][q] = 0.f;

    auto issue = [&](int c) {
        const float* asrc = (c < 4) ? g_mean : X;
        const int k0 = (c & 3) * 32;
        float* dA = sA + (c & 1) * (128 * LDA);
        float* dB = sB + (c & 1) * (128 * LDA);
        #pragma unroll
        for (int t = 0; t < 4; t++) {
            int i = tid + t * 256;
            int r = i >> 3, seg = i & 7;
            int grow = row0 + r;
            if (grow > NN - 1) grow = NN - 1;
            cp16((uint32_t)__cvta_generic_to_shared(dA + r * LDA + seg * 4),
                 asrc + (size_t)grow * 128 + k0 + seg * 4);
            cp16((uint32_t)__cvta_generic_to_shared(dB + r * LDA + seg * 4),
                 g_W1t + r * 256 + c * 32 + seg * 4);
        }
        asm volatile("cp.async.commit_group;" ::: "memory");
    };

    issue(0);
    for (int c = 0; c < 8; c++) {
        if (c < 7) {
            issue(c + 1);
            asm volatile("cp.async.wait_group 1;" ::: "memory");
        } else {
            asm volatile("cp.async.wait_group 0;" ::: "memory");
        }
        __syncthreads();
        const float* A = sA + (c & 1) * (128 * LDA);
        const float* B = sB + (c & 1) * (128 * LDA);
        #pragma unroll
        for (int ks = 0; ks < 4; ks++) {
            const int bk = ks * 8 + (lane & 3);
            float b0[8], b1[8];
            #pragma unroll
            for (int nt = 0; nt < 8; nt++) {
                int n = wn * 64 + nt * 8 + (lane >> 2);
                b0[nt] = B[n * LDA + bk];
                b1[nt] = B[n * LDA + bk + 4];
            }
            #pragma unroll
            for (int mt = 0; mt < 2; mt++) {
                int r = wm * 32 + mt * 16 + (lane >> 2);
                float a0 = f2tf(A[r * LDA + bk]);
                float a1 = f2tf(A[(r + 8) * LDA + bk]);
                float a2 = f2tf(A[r * LDA + bk + 4]);
                float a3 = f2tf(A[(r + 8) * LDA + bk + 4]);
                #pragma unroll
                for (int nt = 0; nt < 8; nt++)
                    mma8(acc[mt][nt], a0, a1, a2, a3, b0[nt], b1[nt]);
            }
        }
        __syncthreads();
    }

    // phase A epilogue: bias+relu -> sH
    #pragma unroll
    for (int mt = 0; mt < 2; mt++) {
        int r = wm * 32 + mt * 16 + (lane >> 2);
        #pragma unroll
        for (int nt = 0; nt < 8; nt++) {
            int cb = wn * 64 + nt * 8 + 2 * (lane & 3);
            sH[r * LDH + cb]           = fmaxf(acc[mt][nt][0] + sBias[cb], 0.f);
            sH[r * LDH + cb + 1]       = fmaxf(acc[mt][nt][1] + sBias[cb + 1], 0.f);
            sH[(r + 8) * LDH + cb]     = fmaxf(acc[mt][nt][2] + sBias[cb], 0.f);
            sH[(r + 8) * LDH + cb + 1] = fmaxf(acc[mt][nt][3] + sBias[cb + 1], 0.f);
        }
    }
    __syncthreads();

    // phase B: [t2|r2] = h @ W2cat (K=128 from smem)
    float acc2[10][4];
    #pragma unroll
    for (int nt = 0; nt < 10; nt++)
        #pragma unroll
        for (int q = 0; q < 4; q++) acc2[nt][q] = 0.f;

    const int r = wid * 16 + (lane >> 2);
    #pragma unroll
    for (int ks = 0; ks < 16; ks++) {
        const int bk = ks * 8 + (lane & 3);
        float a0 = f2tf(sH[r * LDH + bk]);
        float a1 = f2tf(sH[(r + 8) * LDH + bk]);
        float a2 = f2tf(sH[r * LDH + bk + 4]);
        float a3 = f2tf(sH[(r + 8) * LDH + bk + 4]);
        #pragma unroll
        for (int nt = 0; nt < 10; nt++) {
            int n = nt * 8 + (lane >> 2);
            float b0 = sW2[n * LDH + bk];
            float b1 = sW2[n * LDH + bk + 4];
            mma8(acc2[nt], a0, a1, a2, a3, b0, b1);
        }
    }

    int gr = row0 + r;
    #pragma unroll
    for (int nt = 0; nt < 10; nt++) {
        int cb = nt * 8 + 2 * (lane & 3);
        float* base0 = (cb < 40) ? g_t2 + (size_t)gr * 40 + cb
                                 : g_r2 + (size_t)gr * 40 + (cb - 40);
        float* base1 = (cb < 40) ? g_t2 + (size_t)(gr + 8) * 40 + cb
                                 : g_r2 + (size_t)(gr + 8) * 40 + (cb - 40);
        if (gr < NN)     *(float2*)base0 = make_float2(acc2[nt][0], acc2[nt][1]);
        if (gr + 8 < NN) *(float2*)base1 = make_float2(acc2[nt][2], acc2[nt][3]);
    }
}

// ---------------- launcher ----------------
extern "C" void kernel_launch(void* const* d_in, const int* in_sizes, int n_in,
                              void* d_out, int out_size) {
    const float* x    = (const float*)d_in[0];
    const void*  edge = d_in[1];
    const float* W1l  = (const float*)d_in[2];
    const float* W1r  = (const float*)d_in[3];
    const float* b1   = (const float*)d_in[4];
    const float* W2l  = (const float*)d_in[5];
    const float* W2r  = (const float*)d_in[6];
    const float* b2   = (const float*)d_in[7];
    float* out = (float*)d_out;

    static int once = 0;
    if (!once) {
        cudaFuncSetAttribute(gemm_fused, cudaFuncAttributeMaxDynamicSharedMemorySize, GF_SMEM);
        once = 1;
    }

    build_csr<<<CSR_BLOCKS, CSR_THREADS>>>((const unsigned int*)edge, edge,
                                           W1l, W1r, W2l, W2r);
    gather1_kernel<<<(NN * 32 + 255) / 256, 256>>>(x);
    gemm_fused<<<(NN + 127) / 128, 256, GF_SMEM>>>(x, b1);
    gather2_kernel<<<(NN * 10 + 319) / 320, 320>>>(b2, out);
}

// round 11
// speedup vs baseline: 1.0586x; 1.0586x over previous
#include <cuda_runtime.h>
#include <cuda_fp16.h>
#include <cstdint>

#define NN 100000
#define NE 800000
#define LDA 36
#define LDH 132

// ---------------- device scratch ----------------
__device__ float  g_mean[(size_t)NN * 128];  // mean-aggregated x (fp32)
__device__ __half g_xh [(size_t)NN * 128];   // fp16 cache of x (gather1 reads)
__device__ float  g_t2 [(size_t)NN * 40];    // h @ W2l
__device__ float  g_r2 [(size_t)NN * 40];    // h @ W2r
__device__ int    g_icnt[NN];
__device__ float  g_inv [NN];
__device__ int    g_rowptr[NN];
__device__ int    g_cursor[NN];
__device__ int    g_adj [NE];
__device__ int    g_src [NE];
__device__ int    g_dst [NE];
__device__ int    g_bsum[512];
__device__ int    g_is64;
__device__ float  g_W1t[128 * 256];   // B layer1: [n=128][k=256], tf32-rna
__device__ float  g_W2t[80 * 128];    // B layer2: [n=80][k=128], tf32-rna

// ---------------- helpers ----------------
__device__ __forceinline__ float f2tf(float f) {
    unsigned int r;
    asm("cvt.rna.tf32.f32 %0, %1;" : "=r"(r) : "f"(f));
    return __uint_as_float(r);
}
__device__ __forceinline__ void cp16(uint32_t dst, const void* src) {
    asm volatile("cp.async.cg.shared.global [%0], [%1], 16;" :: "r"(dst), "l"(src));
}
__device__ __forceinline__ void mma8(float* c, float a0, float a1, float a2, float a3,
                                     float b0, float b1) {
    asm volatile("mma.sync.aligned.m16n8k8.row.col.f32.tf32.tf32.f32 "
        "{%0,%1,%2,%3}, {%4,%5,%6,%7}, {%8,%9}, {%0,%1,%2,%3};"
        : "+f"(c[0]), "+f"(c[1]), "+f"(c[2]), "+f"(c[3])
        : "r"(__float_as_uint(a0)), "r"(__float_as_uint(a1)),
          "r"(__float_as_uint(a2)), "r"(__float_as_uint(a3)),
          "r"(__float_as_uint(b0)), "r"(__float_as_uint(b1)));
}

// ---------------- init: zero icnt; block 0 detects dtype; low threads prep weights ----------------
__global__ void init_kernel(const unsigned int* __restrict__ w,
                            const float* __restrict__ W1l, const float* __restrict__ W1r,
                            const float* __restrict__ W2l, const float* __restrict__ W2r) {
    int i = blockIdx.x * blockDim.x + threadIdx.x;
    if (i < NN) g_icnt[i] = 0;
    if (blockIdx.x == 0) {
        int nz = 0;
        for (int t = threadIdx.x; t < 2048; t += blockDim.x)
            nz |= (w[2 * t + 1] != 0u);
        nz = __syncthreads_or(nz);
        if (threadIdx.x == 0) g_is64 = (nz == 0) ? 1 : 0;
    }
    if (i < 32768) {
        int k = i >> 7, n = i & 127;
        float v = (k < 128) ? W1l[k * 128 + n] : W1r[(k - 128) * 128 + n];
        g_W1t[n * 256 + k] = f2tf(v);
    } else if (i < 32768 + 10240) {
        int u = i - 32768;
        int k = u / 80, n = u - k * 80;
        float v = (n < 40) ? W2l[k * 40 + n] : W2r[k * 40 + (n - 40)];
        g_W2t[n * 128 + k] = f2tf(v);
    }
}

// ---------------- convert: edges -> int32 src/dst + degrees; x -> fp16 cache ----------------
__global__ void convert_kernel(const void* __restrict__ ei, const float* __restrict__ x) {
    int i = blockIdx.x * blockDim.x + threadIdx.x;     // 800K threads
    if (i < NE) {
        int s, d;
        if (g_is64) {
            const long long* p = (const long long*)ei;
            s = (int)p[i]; d = (int)p[NE + i];
        } else {
            const int* p = (const int*)ei;
            s = p[i]; d = p[NE + i];
        }
        g_src[i] = s;
        g_dst[i] = d;
        atomicAdd(&g_icnt[d], 1);
    }
    // x -> fp16 (grid-stride over NN*32 float4 groups = 3.2M)
    const float4* x4 = (const float4*)x;
    const int total = gridDim.x * blockDim.x;
    for (int q = i; q < NN * 32; q += total) {
        float4 v = x4[q];
        __half2* dsth = (__half2*)(g_xh + (size_t)q * 4);
        dsth[0] = __floats2half2_rn(v.x, v.y);
        dsth[1] = __floats2half2_rn(v.z, v.w);
    }
}

// ---------------- CSR build ----------------
__global__ void scan1() {                    // 391 x 256
    __shared__ int sh[256];
    int i = blockIdx.x * 256 + threadIdx.x;
    sh[threadIdx.x] = (i < NN) ? g_icnt[i] : 0;
    for (int o = 128; o > 0; o >>= 1) {
        __syncthreads();
        if (threadIdx.x < o) sh[threadIdx.x] += sh[threadIdx.x + o];
    }
    if (threadIdx.x == 0) g_bsum[blockIdx.x] = sh[0];
}

__global__ void scan23() {                   // 391 x 512
    __shared__ int sb[512];
    __shared__ int sh[256];
    int t = threadIdx.x;
    sb[t] = (t < 391) ? g_bsum[t] : 0;
    __syncthreads();
    #pragma unroll
    for (int o = 1; o < 512; o <<= 1) {
        int v = (t >= o) ? sb[t - o] : 0;
        __syncthreads();
        sb[t] += v;
        __syncthreads();
    }
    int blockoff = blockIdx.x ? sb[blockIdx.x - 1] : 0;

    int i = blockIdx.x * 256 + t;
    int v = 0;
    if (t < 256) {
        v = (i < NN) ? g_icnt[i] : 0;
        sh[t] = v;
    }
    __syncthreads();
    #pragma unroll
    for (int o = 1; o < 256; o <<= 1) {
        int u = (t < 256 && t >= o) ? sh[t - o] : 0;
        __syncthreads();
        if (t < 256) sh[t] += u;
        __syncthreads();
    }
    if (t < 256 && i < NN) {
        int excl = blockoff + sh[t] - v;
        g_rowptr[i] = excl;
        g_cursor[i] = excl;
        g_inv[i] = 1.0f / fmaxf((float)v, 1.0f);
    }
}

__global__ void fill_kernel() {
    int i = blockIdx.x * blockDim.x + threadIdx.x;
    if (i >= NE) return;
    int slot = atomicAdd(&g_cursor[g_dst[i]], 1);
    g_adj[slot] = g_src[i];
}

// ---------------- gather layer 1: warp per node, fp16 x-cache ----------------
__global__ void __launch_bounds__(256) gather1_kernel() {
    int node = (blockIdx.x * blockDim.x + threadIdx.x) >> 5;
    int lane = threadIdx.x & 31;
    if (node >= NN) return;
    int beg = g_rowptr[node];
    int end = beg + g_icnt[node];
    const uint2* xh = (const uint2*)g_xh;    // 4 halves per uint2, lane-coalesced
    float4 acc = {0.f, 0.f, 0.f, 0.f};
    int j = beg;
    for (; j + 4 <= end; j += 4) {
        int s0 = __ldg(&g_adj[j]);
        int s1 = __ldg(&g_adj[j + 1]);
        int s2 = __ldg(&g_adj[j + 2]);
        int s3 = __ldg(&g_adj[j + 3]);
        uint2 u0 = xh[(size_t)s0 * 32 + lane];
        uint2 u1 = xh[(size_t)s1 * 32 + lane];
        uint2 u2 = xh[(size_t)s2 * 32 + lane];
        uint2 u3 = xh[(size_t)s3 * 32 + lane];
        #pragma unroll
        for (int q = 0; q < 4; q++) {
            uint2 u = (q == 0) ? u0 : (q == 1) ? u1 : (q == 2) ? u2 : u3;
            float2 fa = __half22float2(*(__half2*)&u.x);
            float2 fb = __half22float2(*(__half2*)&u.y);
            acc.x += fa.x; acc.y += fa.y; acc.z += fb.x; acc.w += fb.y;
        }
    }
    for (; j < end; j++) {
        int s = __ldg(&g_adj[j]);
        uint2 u = xh[(size_t)s * 32 + lane];
        float2 fa = __half22float2(*(__half2*)&u.x);
        float2 fb = __half22float2(*(__half2*)&u.y);
        acc.x += fa.x; acc.y += fa.y; acc.z += fb.x; acc.w += fb.y;
    }
    float iv = g_inv[node];
    acc.x *= iv; acc.y *= iv; acc.z *= iv; acc.w *= iv;
    ((float4*)g_mean)[(size_t)node * 32 + lane] = acc;
}

// ---------------- gather layer 2 + epilogue (MLP-8) ----------------
__global__ void __launch_bounds__(320) gather2_kernel(const float* __restrict__ b2,
                                                      float* __restrict__ out) {
    int i = blockIdx.x * blockDim.x + threadIdx.x;
    if (i >= NN * 10) return;
    int node = i / 10;
    int c = i - node * 10;
    int beg = g_rowptr[node];
    int end = beg + g_icnt[node];
    const float4* t4 = (const float4*)g_t2;
    float4 acc = {0.f, 0.f, 0.f, 0.f};
    int j = beg;
    for (; j + 8 <= end; j += 8) {
        int s[8];
        #pragma unroll
        for (int q = 0; q < 8; q++) s[q] = __ldg(&g_adj[j + q]);
        float4 v[8];
        #pragma unroll
        for (int q = 0; q < 8; q++) v[q] = t4[(size_t)s[q] * 10 + c];
        #pragma unroll
        for (int q = 0; q < 8; q++) {
            acc.x += v[q].x; acc.y += v[q].y; acc.z += v[q].z; acc.w += v[q].w;
        }
    }
    if (j + 4 <= end) {
        int s[4];
        #pragma unroll
        for (int q = 0; q < 4; q++) s[q] = __ldg(&g_adj[j + q]);
        float4 v[4];
        #pragma unroll
        for (int q = 0; q < 4; q++) v[q] = t4[(size_t)s[q] * 10 + c];
        #pragma unroll
        for (int q = 0; q < 4; q++) {
            acc.x += v[q].x; acc.y += v[q].y; acc.z += v[q].z; acc.w += v[q].w;
        }
        j += 4;
    }
    for (; j < end; j++) {
        int s = __ldg(&g_adj[j]);
        float4 v = t4[(size_t)s * 10 + c];
        acc.x += v.x; acc.y += v.y; acc.z += v.z; acc.w += v.w;
    }
    float iv = g_inv[node];
    float4 r = ((const float4*)g_r2)[i];
    float4 b = ((const float4*)b2)[c];
    float4 o;
    o.x = acc.x * iv + r.x + b.x;
    o.y = acc.y * iv + r.y + b.y;
    o.z = acc.z * iv + r.z + b.z;
    o.w = acc.w * iv + r.w + b.w;
    ((float4*)out)[i] = o;
}

// ---------------- fused GEMM (R6 config: full SMEM staging, 1 CTA/SM) ----------------
#define SM_A  0
#define SM_B  (2 * 128 * LDA)
#define SM_H  (SM_B + 2 * 128 * LDA)
#define SM_W2 (SM_H + 128 * LDH)
#define SM_BI (SM_W2 + 80 * LDH)
#define GF_SMEM ((SM_BI + 128) * 4)
__global__ void __launch_bounds__(256) gemm_fused(const float* __restrict__ X,
                                                  const float* __restrict__ bias) {
    extern __shared__ float smem[];
    float* sA = smem + SM_A;
    float* sB = smem + SM_B;
    float* sH = smem + SM_H;
    float* sW2 = smem + SM_W2;
    float* sBias = smem + SM_BI;

    const int tid = threadIdx.x, lane = tid & 31, wid = tid >> 5;
    const int wm = wid & 3, wn = wid >> 2;
    const int row0 = blockIdx.x * 128;
    if (tid < 128) sBias[tid] = bias[tid];

    {   // stage W2 [80][128] -> sW2 [80][LDH]
        const float4* src = (const float4*)g_W2t;
        #pragma unroll
        for (int t = 0; t < 10; t++) {
            int i = tid + t * 256;
            int n = i >> 5, kq = i & 31;
            ((float4*)sW2)[n * (LDH / 4) + kq] = src[i];
        }
    }

    float acc[2][8][4];
    #pragma unroll
    for (int mt = 0; mt < 2; mt++)
        #pragma unroll
        for (int nt = 0; nt < 8; nt++)
            #pragma unroll
            for (int q = 0; q < 4; q++) acc[mt][nt][q] = 0.f;

    auto issue = [&](int c) {
        const float* asrc = (c < 4) ? g_mean : X;
        const int k0 = (c & 3) * 32;
        float* dA = sA + (c & 1) * (128 * LDA);
        float* dB = sB + (c & 1) * (128 * LDA);
        #pragma unroll
        for (int t = 0; t < 4; t++) {
            int i = tid + t * 256;
            int r = i >> 3, seg = i & 7;
            int grow = row0 + r;
            if (grow > NN - 1) grow = NN - 1;
            cp16((uint32_t)__cvta_generic_to_shared(dA + r * LDA + seg * 4),
                 asrc + (size_t)grow * 128 + k0 + seg * 4);
            cp16((uint32_t)__cvta_generic_to_shared(dB + r * LDA + seg * 4),
                 g_W1t + r * 256 + c * 32 + seg * 4);
        }
        asm volatile("cp.async.commit_group;" ::: "memory");
    };

    issue(0);
    for (int c = 0; c < 8; c++) {
        if (c < 7) {
            issue(c + 1);
            asm volatile("cp.async.wait_group 1;" ::: "memory");
        } else {
            asm volatile("cp.async.wait_group 0;" ::: "memory");
        }
        __syncthreads();
        const float* A = sA + (c & 1) * (128 * LDA);
        const float* B = sB + (c & 1) * (128 * LDA);
        #pragma unroll
        for (int ks = 0; ks < 4; ks++) {
            const int bk = ks * 8 + (lane & 3);
            float b0[8], b1[8];
            #pragma unroll
            for (int nt = 0; nt < 8; nt++) {
                int n = wn * 64 + nt * 8 + (lane >> 2);
                b0[nt] = B[n * LDA + bk];
                b1[nt] = B[n * LDA + bk + 4];
            }
            #pragma unroll
            for (int mt = 0; mt < 2; mt++) {
                int r = wm * 32 + mt * 16 + (lane >> 2);
                float a0 = f2tf(A[r * LDA + bk]);
                float a1 = f2tf(A[(r + 8) * LDA + bk]);
                float a2 = f2tf(A[r * LDA + bk + 4]);
                float a3 = f2tf(A[(r + 8) * LDA + bk + 4]);
                #pragma unroll
                for (int nt = 0; nt < 8; nt++)
                    mma8(acc[mt][nt], a0, a1, a2, a3, b0[nt], b1[nt]);
            }
        }
        __syncthreads();
    }

    // phase A epilogue: bias+relu -> sH
    #pragma unroll
    for (int mt = 0; mt < 2; mt++) {
        int r = wm * 32 + mt * 16 + (lane >> 2);
        #pragma unroll
        for (int nt = 0; nt < 8; nt++) {
            int cb = wn * 64 + nt * 8 + 2 * (lane & 3);
            sH[r * LDH + cb]           = fmaxf(acc[mt][nt][0] + sBias[cb], 0.f);
            sH[r * LDH + cb + 1]       = fmaxf(acc[mt][nt][1] + sBias[cb + 1], 0.f);
            sH[(r + 8) * LDH + cb]     = fmaxf(acc[mt][nt][2] + sBias[cb], 0.f);
            sH[(r + 8) * LDH + cb + 1] = fmaxf(acc[mt][nt][3] + sBias[cb + 1], 0.f);
        }
    }
    __syncthreads();

    // phase B: [t2|r2] = h @ W2cat (K=128 from smem)
    float acc2[10][4];
    #pragma unroll
    for (int nt = 0; nt < 10; nt++)
        #pragma unroll
        for (int q = 0; q < 4; q++) acc2[nt][q] = 0.f;

    const int r = wid * 16 + (lane >> 2);
    #pragma unroll
    for (int ks = 0; ks < 16; ks++) {
        const int bk = ks * 8 + (lane & 3);
        float a0 = f2tf(sH[r * LDH + bk]);
        float a1 = f2tf(sH[(r + 8) * LDH + bk]);
        float a2 = f2tf(sH[r * LDH + bk + 4]);
        float a3 = f2tf(sH[(r + 8) * LDH + bk + 4]);
        #pragma unroll
        for (int nt = 0; nt < 10; nt++) {
            int n = nt * 8 + (lane >> 2);
            float b0 = sW2[n * LDH + bk];
            float b1 = sW2[n * LDH + bk + 4];
            mma8(acc2[nt], a0, a1, a2, a3, b0, b1);
        }
    }

    int gr = row0 + r;
    #pragma unroll
    for (int nt = 0; nt < 10; nt++) {
        int cb = nt * 8 + 2 * (lane & 3);
        float* base0 = (cb < 40) ? g_t2 + (size_t)gr * 40 + cb
                                 : g_r2 + (size_t)gr * 40 + (cb - 40);
        float* base1 = (cb < 40) ? g_t2 + (size_t)(gr + 8) * 40 + cb
                                 : g_r2 + (size_t)(gr + 8) * 40 + (cb - 40);
        if (gr < NN)     *(float2*)base0 = make_float2(acc2[nt][0], acc2[nt][1]);
        if (gr + 8 < NN) *(float2*)base1 = make_float2(acc2[nt][2], acc2[nt][3]);
    }
}

// ---------------- launcher ----------------
extern "C" void kernel_launch(void* const* d_in, const int* in_sizes, int n_in,
                              void* d_out, int out_size) {
    const float* x    = (const float*)d_in[0];
    const void*  edge = d_in[1];
    const float* W1l  = (const float*)d_in[2];
    const float* W1r  = (const float*)d_in[3];
    const float* b1   = (const float*)d_in[4];
    const float* W2l  = (const float*)d_in[5];
    const float* W2r  = (const float*)d_in[6];
    const float* b2   = (const float*)d_in[7];
    float* out = (float*)d_out;

    static int once = 0;
    if (!once) {
        cudaFuncSetAttribute(gemm_fused, cudaFuncAttributeMaxDynamicSharedMemorySize, GF_SMEM);
        once = 1;
    }

    const int NBLK = (NN + 255) / 256;       // 391

    init_kernel<<<NBLK, 256>>>((const unsigned int*)edge, W1l, W1r, W2l, W2r);
    convert_kernel<<<(NE + 255) / 256, 256>>>(edge, x);
    scan1<<<NBLK, 256>>>();
    scan23<<<NBLK, 512>>>();
    fill_kernel<<<(NE + 255) / 256, 256>>>();
    gather1_kernel<<<(NN * 32 + 255) / 256, 256>>>();
    gemm_fused<<<(NN + 127) / 128, 256, GF_SMEM>>>(x, b1);
    gather2_kernel<<<(NN * 10 + 319) / 320, 320>>>(b2, out);
}

// round 12
// speedup vs baseline: 1.1091x; 1.0477x over previous
#include <cuda_runtime.h>
#include <cuda_fp16.h>
#include <cstdint>

#define NN 100000
#define NE 800000
#define LDA 36
#define LDH 132

// ---------------- device scratch ----------------
__device__ float  g_mean[(size_t)NN * 128];  // mean-aggregated x (fp32)
__device__ __half g_xh [(size_t)NN * 128];   // fp16 cache of x (gather1 reads)
__device__ __half g_t2h[(size_t)NN * 40];    // h @ W2l (fp16; mean-averaged later)
__device__ float  g_r2 [(size_t)NN * 40];    // h @ W2r (fp32; direct output term)
__device__ int    g_icnt[NN];
__device__ float  g_inv [NN];
__device__ int    g_rowptr[NN];
__device__ int    g_cursor[NN];
__device__ int    g_adj [NE];
__device__ int    g_src [NE];
__device__ int    g_dst [NE];
__device__ int    g_bsum[512];
__device__ int    g_is64;
__device__ float  g_W1t[128 * 256];   // B layer1: [n=128][k=256], tf32-rna
__device__ float  g_W2t[80 * 128];    // B layer2: [n=80][k=128], tf32-rna

// ---------------- helpers ----------------
__device__ __forceinline__ float f2tf(float f) {
    unsigned int r;
    asm("cvt.rna.tf32.f32 %0, %1;" : "=r"(r) : "f"(f));
    return __uint_as_float(r);
}
__device__ __forceinline__ void cp16(uint32_t dst, const void* src) {
    asm volatile("cp.async.cg.shared.global [%0], [%1], 16;" :: "r"(dst), "l"(src));
}
__device__ __forceinline__ void mma8(float* c, float a0, float a1, float a2, float a3,
                                     float b0, float b1) {
    asm volatile("mma.sync.aligned.m16n8k8.row.col.f32.tf32.tf32.f32 "
        "{%0,%1,%2,%3}, {%4,%5,%6,%7}, {%8,%9}, {%0,%1,%2,%3};"
        : "+f"(c[0]), "+f"(c[1]), "+f"(c[2]), "+f"(c[3])
        : "r"(__float_as_uint(a0)), "r"(__float_as_uint(a1)),
          "r"(__float_as_uint(a2)), "r"(__float_as_uint(a3)),
          "r"(__float_as_uint(b0)), "r"(__float_as_uint(b1)));
}

// ---------------- init: zero icnt; block 0 detects dtype; low threads prep weights ----------------
__global__ void init_kernel(const unsigned int* __restrict__ w,
                            const float* __restrict__ W1l, const float* __restrict__ W1r,
                            const float* __restrict__ W2l, const float* __restrict__ W2r) {
    int i = blockIdx.x * blockDim.x + threadIdx.x;
    if (i < NN) g_icnt[i] = 0;
    if (blockIdx.x == 0) {
        int nz = 0;
        for (int t = threadIdx.x; t < 2048; t += blockDim.x)
            nz |= (w[2 * t + 1] != 0u);
        nz = __syncthreads_or(nz);
        if (threadIdx.x == 0) g_is64 = (nz == 0) ? 1 : 0;
    }
    if (i < 32768) {
        int k = i >> 7, n = i & 127;
        float v = (k < 128) ? W1l[k * 128 + n] : W1r[(k - 128) * 128 + n];
        g_W1t[n * 256 + k] = f2tf(v);
    } else if (i < 32768 + 10240) {
        int u = i - 32768;
        int k = u / 80, n = u - k * 80;
        float v = (n < 40) ? W2l[k * 40 + n] : W2r[k * 40 + (n - 40)];
        g_W2t[n * 128 + k] = f2tf(v);
    }
}

// ---------------- convert: edges -> int32 src/dst + degrees; x -> fp16 cache ----------------
__global__ void convert_kernel(const void* __restrict__ ei, const float* __restrict__ x) {
    int i = blockIdx.x * blockDim.x + threadIdx.x;     // 800K threads
    if (i < NE) {
        int s, d;
        if (g_is64) {
            const long long* p = (const long long*)ei;
            s = (int)p[i]; d = (int)p[NE + i];
        } else {
            const int* p = (const int*)ei;
            s = p[i]; d = p[NE + i];
        }
        g_src[i] = s;
        g_dst[i] = d;
        atomicAdd(&g_icnt[d], 1);
    }
    const float4* x4 = (const float4*)x;
    const int total = gridDim.x * blockDim.x;
    for (int q = i; q < NN * 32; q += total) {
        float4 v = x4[q];
        __half2* dsth = (__half2*)(g_xh + (size_t)q * 4);
        dsth[0] = __floats2half2_rn(v.x, v.y);
        dsth[1] = __floats2half2_rn(v.z, v.w);
    }
}

// ---------------- CSR build ----------------
__global__ void scan1() {                    // 391 x 256
    __shared__ int sh[256];
    int i = blockIdx.x * 256 + threadIdx.x;
    sh[threadIdx.x] = (i < NN) ? g_icnt[i] : 0;
    for (int o = 128; o > 0; o >>= 1) {
        __syncthreads();
        if (threadIdx.x < o) sh[threadIdx.x] += sh[threadIdx.x + o];
    }
    if (threadIdx.x == 0) g_bsum[blockIdx.x] = sh[0];
}

__global__ void scan23() {                   // 391 x 512
    __shared__ int sb[512];
    __shared__ int sh[256];
    int t = threadIdx.x;
    sb[t] = (t < 391) ? g_bsum[t] : 0;
    __syncthreads();
    #pragma unroll
    for (int o = 1; o < 512; o <<= 1) {
        int v = (t >= o) ? sb[t - o] : 0;
        __syncthreads();
        sb[t] += v;
        __syncthreads();
    }
    int blockoff = blockIdx.x ? sb[blockIdx.x - 1] : 0;

    int i = blockIdx.x * 256 + t;
    int v = 0;
    if (t < 256) {
        v = (i < NN) ? g_icnt[i] : 0;
        sh[t] = v;
    }
    __syncthreads();
    #pragma unroll
    for (int o = 1; o < 256; o <<= 1) {
        int u = (t < 256 && t >= o) ? sh[t - o] : 0;
        __syncthreads();
        if (t < 256) sh[t] += u;
        __syncthreads();
    }
    if (t < 256 && i < NN) {
        int excl = blockoff + sh[t] - v;
        g_rowptr[i] = excl;
        g_cursor[i] = excl;
        g_inv[i] = 1.0f / fmaxf((float)v, 1.0f);
    }
}

__global__ void fill_kernel() {
    int i = blockIdx.x * blockDim.x + threadIdx.x;
    if (i >= NE) return;
    int slot = atomicAdd(&g_cursor[g_dst[i]], 1);
    g_adj[slot] = g_src[i];
}

// ---------------- gather layer 1: warp per node, fp16 x-cache ----------------
__global__ void __launch_bounds__(256) gather1_kernel() {
    int node = (blockIdx.x * blockDim.x + threadIdx.x) >> 5;
    int lane = threadIdx.x & 31;
    if (node >= NN) return;
    int beg = g_rowptr[node];
    int end = beg + g_icnt[node];
    const uint2* xh = (const uint2*)g_xh;
    float4 acc = {0.f, 0.f, 0.f, 0.f};
    int j = beg;
    for (; j + 4 <= end; j += 4) {
        int s0 = __ldg(&g_adj[j]);
        int s1 = __ldg(&g_adj[j + 1]);
        int s2 = __ldg(&g_adj[j + 2]);
        int s3 = __ldg(&g_adj[j + 3]);
        uint2 u0 = xh[(size_t)s0 * 32 + lane];
        uint2 u1 = xh[(size_t)s1 * 32 + lane];
        uint2 u2 = xh[(size_t)s2 * 32 + lane];
        uint2 u3 = xh[(size_t)s3 * 32 + lane];
        #pragma unroll
        for (int q = 0; q < 4; q++) {
            uint2 u = (q == 0) ? u0 : (q == 1) ? u1 : (q == 2) ? u2 : u3;
            float2 fa = __half22float2(*(__half2*)&u.x);
            float2 fb = __half22float2(*(__half2*)&u.y);
            acc.x += fa.x; acc.y += fa.y; acc.z += fb.x; acc.w += fb.y;
        }
    }
    for (; j < end; j++) {
        int s = __ldg(&g_adj[j]);
        uint2 u = xh[(size_t)s * 32 + lane];
        float2 fa = __half22float2(*(__half2*)&u.x);
        float2 fb = __half22float2(*(__half2*)&u.y);
        acc.x += fa.x; acc.y += fa.y; acc.z += fb.x; acc.w += fb.y;
    }
    float iv = g_inv[node];
    acc.x *= iv; acc.y *= iv; acc.z *= iv; acc.w *= iv;
    ((float4*)g_mean)[(size_t)node * 32 + lane] = acc;
}

// ---------------- gather layer 2 + epilogue (fp16 t2, MLP-8) ----------------
__global__ void __launch_bounds__(320) gather2_kernel(const float* __restrict__ b2,
                                                      float* __restrict__ out) {
    int i = blockIdx.x * blockDim.x + threadIdx.x;
    if (i >= NN * 10) return;
    int node = i / 10;
    int c = i - node * 10;
    int beg = g_rowptr[node];
    int end = beg + g_icnt[node];
    const uint2* t2h = (const uint2*)g_t2h;   // 4 halves per uint2; row = 10 uint2
    float4 acc = {0.f, 0.f, 0.f, 0.f};
    int j = beg;
    for (; j + 8 <= end; j += 8) {
        int s[8];
        #pragma unroll
        for (int q = 0; q < 8; q++) s[q] = __ldg(&g_adj[j + q]);
        uint2 v[8];
        #pragma unroll
        for (int q = 0; q < 8; q++) v[q] = t2h[(size_t)s[q] * 10 + c];
        #pragma unroll
        for (int q = 0; q < 8; q++) {
            float2 fa = __half22float2(*(__half2*)&v[q].x);
            float2 fb = __half22float2(*(__half2*)&v[q].y);
            acc.x += fa.x; acc.y += fa.y; acc.z += fb.x; acc.w += fb.y;
        }
    }
    if (j + 4 <= end) {
        int s[4];
        #pragma unroll
        for (int q = 0; q < 4; q++) s[q] = __ldg(&g_adj[j + q]);
        uint2 v[4];
        #pragma unroll
        for (int q = 0; q < 4; q++) v[q] = t2h[(size_t)s[q] * 10 + c];
        #pragma unroll
        for (int q = 0; q < 4; q++) {
            float2 fa = __half22float2(*(__half2*)&v[q].x);
            float2 fb = __half22float2(*(__half2*)&v[q].y);
            acc.x += fa.x; acc.y += fa.y; acc.z += fb.x; acc.w += fb.y;
        }
        j += 4;
    }
    for (; j < end; j++) {
        int s = __ldg(&g_adj[j]);
        uint2 u = t2h[(size_t)s * 10 + c];
        float2 fa = __half22float2(*(__half2*)&u.x);
        float2 fb = __half22float2(*(__half2*)&u.y);
        acc.x += fa.x; acc.y += fa.y; acc.z += fb.x; acc.w += fb.y;
    }
    float iv = g_inv[node];
    float4 r = ((const float4*)g_r2)[i];
    float4 b = ((const float4*)b2)[c];
    float4 o;
    o.x = acc.x * iv + r.x + b.x;
    o.y = acc.y * iv + r.y + b.y;
    o.z = acc.z * iv + r.z + b.z;
    o.w = acc.w * iv + r.w + b.w;
    ((float4*)out)[i] = o;
}

// ---------------- fused GEMM (R6 config: full SMEM staging, 1 CTA/SM) ----------------
#define SM_A  0
#define SM_B  (2 * 128 * LDA)
#define SM_H  (SM_B + 2 * 128 * LDA)
#define SM_W2 (SM_H + 128 * LDH)
#define SM_BI (SM_W2 + 80 * LDH)
#define GF_SMEM ((SM_BI + 128) * 4)
__global__ void __launch_bounds__(256) gemm_fused(const float* __restrict__ X,
                                                  const float* __restrict__ bias) {
    extern __shared__ float smem[];
    float* sA = smem + SM_A;
    float* sB = smem + SM_B;
    float* sH = smem + SM_H;
    float* sW2 = smem + SM_W2;
    float* sBias = smem + SM_BI;

    const int tid = threadIdx.x, lane = tid & 31, wid = tid >> 5;
    const int wm = wid & 3, wn = wid >> 2;
    const int row0 = blockIdx.x * 128;
    if (tid < 128) sBias[tid] = bias[tid];

    {   // stage W2 [80][128] -> sW2 [80][LDH]
        const float4* src = (const float4*)g_W2t;
        #pragma unroll
        for (int t = 0; t < 10; t++) {
            int i = tid + t * 256;
            int n = i >> 5, kq = i & 31;
            ((float4*)sW2)[n * (LDH / 4) + kq] = src[i];
        }
    }

    float acc[2][8][4];
    #pragma unroll
    for (int mt = 0; mt < 2; mt++)
        #pragma unroll
        for (int nt = 0; nt < 8; nt++)
            #pragma unroll
            for (int q = 0; q < 4; q++) acc[mt][nt][q] = 0.f;

    auto issue = [&](int c) {
        const float* asrc = (c < 4) ? g_mean : X;
        const int k0 = (c & 3) * 32;
        float* dA = sA + (c & 1) * (128 * LDA);
        float* dB = sB + (c & 1) * (128 * LDA);
        #pragma unroll
        for (int t = 0; t < 4; t++) {
            int i = tid + t * 256;
            int r = i >> 3, seg = i & 7;
            int grow = row0 + r;
            if (grow > NN - 1) grow = NN - 1;
            cp16((uint32_t)__cvta_generic_to_shared(dA + r * LDA + seg * 4),
                 asrc + (size_t)grow * 128 + k0 + seg * 4);
            cp16((uint32_t)__cvta_generic_to_shared(dB + r * LDA + seg * 4),
                 g_W1t + r * 256 + c * 32 + seg * 4);
        }
        asm volatile("cp.async.commit_group;" ::: "memory");
    };

    issue(0);
    for (int c = 0; c < 8; c++) {
        if (c < 7) {
            issue(c + 1);
            asm volatile("cp.async.wait_group 1;" ::: "memory");
        } else {
            asm volatile("cp.async.wait_group 0;" ::: "memory");
        }
        __syncthreads();
        const float* A = sA + (c & 1) * (128 * LDA);
        const float* B = sB + (c & 1) * (128 * LDA);
        #pragma unroll
        for (int ks = 0; ks < 4; ks++) {
            const int bk = ks * 8 + (lane & 3);
            float b0[8], b1[8];
            #pragma unroll
            for (int nt = 0; nt < 8; nt++) {
                int n = wn * 64 + nt * 8 + (lane >> 2);
                b0[nt] = B[n * LDA + bk];
                b1[nt] = B[n * LDA + bk + 4];
            }
            #pragma unroll
            for (int mt = 0; mt < 2; mt++) {
                int r = wm * 32 + mt * 16 + (lane >> 2);
                float a0 = f2tf(A[r * LDA + bk]);
                float a1 = f2tf(A[(r + 8) * LDA + bk]);
                float a2 = f2tf(A[r * LDA + bk + 4]);
                float a3 = f2tf(A[(r + 8) * LDA + bk + 4]);
                #pragma unroll
                for (int nt = 0; nt < 8; nt++)
                    mma8(acc[mt][nt], a0, a1, a2, a3, b0[nt], b1[nt]);
            }
        }
        __syncthreads();
    }

    // phase A epilogue: bias+relu -> sH
    #pragma unroll
    for (int mt = 0; mt < 2; mt++) {
        int r = wm * 32 + mt * 16 + (lane >> 2);
        #pragma unroll
        for (int nt = 0; nt < 8; nt++) {
            int cb = wn * 64 + nt * 8 + 2 * (lane & 3);
            sH[r * LDH + cb]           = fmaxf(acc[mt][nt][0] + sBias[cb], 0.f);
            sH[r * LDH + cb + 1]       = fmaxf(acc[mt][nt][1] + sBias[cb + 1], 0.f);
            sH[(r + 8) * LDH + cb]     = fmaxf(acc[mt][nt][2] + sBias[cb], 0.f);
            sH[(r + 8) * LDH + cb + 1] = fmaxf(acc[mt][nt][3] + sBias[cb + 1], 0.f);
        }
    }
    __syncthreads();

    // phase B: [t2|r2] = h @ W2cat (K=128 from smem)
    float acc2[10][4];
    #pragma unroll
    for (int nt = 0; nt < 10; nt++)
        #pragma unroll
        for (int q = 0; q < 4; q++) acc2[nt][q] = 0.f;

    const int r = wid * 16 + (lane >> 2);
    #pragma unroll
    for (int ks = 0; ks < 16; ks++) {
        const int bk = ks * 8 + (lane & 3);
        float a0 = f2tf(sH[r * LDH + bk]);
        float a1 = f2tf(sH[(r + 8) * LDH + bk]);
        float a2 = f2tf(sH[r * LDH + bk + 4]);
        float a3 = f2tf(sH[(r + 8) * LDH + bk + 4]);
        #pragma unroll
        for (int nt = 0; nt < 10; nt++) {
            int n = nt * 8 + (lane >> 2);
            float b0 = sW2[n * LDH + bk];
            float b1 = sW2[n * LDH + bk + 4];
            mma8(acc2[nt], a0, a1, a2, a3, b0, b1);
        }
    }

    int gr = row0 + r;
    #pragma unroll
    for (int nt = 0; nt < 10; nt++) {
        int cb = nt * 8 + 2 * (lane & 3);
        if (cb < 40) {
            // t2 in fp16 (mean-averaged downstream; quantization benign)
            if (gr < NN)
                *(__half2*)(g_t2h + (size_t)gr * 40 + cb) =
                    __floats2half2_rn(acc2[nt][0], acc2[nt][1]);
            if (gr + 8 < NN)
                *(__half2*)(g_t2h + (size_t)(gr + 8) * 40 + cb) =
                    __floats2half2_rn(acc2[nt][2], acc2[nt][3]);
        } else {
            int cr = cb - 40;
            if (gr < NN)
                *(float2*)(g_r2 + (size_t)gr * 40 + cr) =
                    make_float2(acc2[nt][0], acc2[nt][1]);
            if (gr + 8 < NN)
                *(float2*)(g_r2 + (size_t)(gr + 8) * 40 + cr) =
                    make_float2(acc2[nt][2], acc2[nt][3]);
        }
    }
}

// ---------------- launcher ----------------
extern "C" void kernel_launch(void* const* d_in, const int* in_sizes, int n_in,
                              void* d_out, int out_size) {
    const float* x    = (const float*)d_in[0];
    const void*  edge = d_in[1];
    const float* W1l  = (const float*)d_in[2];
    const float* W1r  = (const float*)d_in[3];
    const float* b1   = (const float*)d_in[4];
    const float* W2l  = (const float*)d_in[5];
    const float* W2r  = (const float*)d_in[6];
    const float* b2   = (const float*)d_in[7];
    float* out = (float*)d_out;

    static int once = 0;
    if (!once) {
        cudaFuncSetAttribute(gemm_fused, cudaFuncAttributeMaxDynamicSharedMemorySize, GF_SMEM);
        once = 1;
    }

    const int NBLK = (NN + 255) / 256;       // 391

    init_kernel<<<NBLK, 256>>>((const unsigned int*)edge, W1l, W1r, W2l, W2r);
    convert_kernel<<<(NE + 255) / 256, 256>>>(edge, x);
    scan1<<<NBLK, 256>>>();
    scan23<<<NBLK, 512>>>();
    fill_kernel<<<(NE + 255) / 256, 256>>>();
    gather1_kernel<<<(NN * 32 + 255) / 256, 256>>>();
    gemm_fused<<<(NN + 127) / 128, 256, GF_SMEM>>>(x, b1);
    gather2_kernel<<<(NN * 10 + 319) / 320, 320>>>(b2, out);
}

// round 13
// speedup vs baseline: 1.4114x; 1.2726x over previous
#include <cuda_runtime.h>
#include <cuda_fp16.h>
#include <cstdint>

#define NN 100000
#define NE 800000
#define LKA 40    // halves per row: A/B K-chunk tiles (32 + 8 pad)
#define LKH 136   // halves per row: sH / sW2 (128 + 8 pad)

// ---------------- device scratch ----------------
__device__ __half g_meanh[(size_t)NN * 128]; // mean-aggregated x (fp16)
__device__ __half g_xh [(size_t)NN * 128];   // fp16 cache of x
__device__ __half g_t2h[(size_t)NN * 40];    // h @ W2l (fp16)
__device__ float  g_r2 [(size_t)NN * 40];    // h @ W2r (fp32)
__device__ int    g_icnt[NN];
__device__ float  g_inv [NN];
__device__ int    g_rowptr[NN];
__device__ int    g_cursor[NN];
__device__ int    g_adj [NE];
__device__ int    g_src [NE];
__device__ int    g_dst [NE];
__device__ int    g_bsum[512];
__device__ int    g_is64;
__device__ __half g_W1h[128 * 256];   // B layer1: [n=128][k=256] fp16
__device__ __half g_W2h[80 * 128];    // B layer2: [n=80][k=128] fp16

// ---------------- helpers ----------------
__device__ __forceinline__ void cp16(uint32_t dst, const void* src) {
    asm volatile("cp.async.cg.shared.global [%0], [%1], 16;" :: "r"(dst), "l"(src));
}
__device__ __forceinline__ void mma16(float* c, uint32_t a0, uint32_t a1,
                                      uint32_t a2, uint32_t a3,
                                      uint32_t b0, uint32_t b1) {
    asm volatile("mma.sync.aligned.m16n8k16.row.col.f32.f16.f16.f32 "
        "{%0,%1,%2,%3}, {%4,%5,%6,%7}, {%8,%9}, {%0,%1,%2,%3};"
        : "+f"(c[0]), "+f"(c[1]), "+f"(c[2]), "+f"(c[3])
        : "r"(a0), "r"(a1), "r"(a2), "r"(a3), "r"(b0), "r"(b1));
}

// ---------------- init: zero icnt; detect dtype; prep fp16 weights ----------------
__global__ void init_kernel(const unsigned int* __restrict__ w,
                            const float* __restrict__ W1l, const float* __restrict__ W1r,
                            const float* __restrict__ W2l, const float* __restrict__ W2r) {
    int i = blockIdx.x * blockDim.x + threadIdx.x;
    if (i < NN) g_icnt[i] = 0;
    if (blockIdx.x == 0) {
        int nz = 0;
        for (int t = threadIdx.x; t < 2048; t += blockDim.x)
            nz |= (w[2 * t + 1] != 0u);
        nz = __syncthreads_or(nz);
        if (threadIdx.x == 0) g_is64 = (nz == 0) ? 1 : 0;
    }
    if (i < 32768) {
        int k = i >> 7, n = i & 127;
        float v = (k < 128) ? W1l[k * 128 + n] : W1r[(k - 128) * 128 + n];
        g_W1h[n * 256 + k] = __float2half_rn(v);
    } else if (i < 32768 + 10240) {
        int u = i - 32768;
        int k = u / 80, n = u - k * 80;
        float v = (n < 40) ? W2l[k * 40 + n] : W2r[k * 40 + (n - 40)];
        g_W2h[n * 128 + k] = __float2half_rn(v);
    }
}

// ---------------- convert: edges -> src/dst + degrees; x -> fp16 ----------------
__global__ void convert_kernel(const void* __restrict__ ei, const float* __restrict__ x) {
    int i = blockIdx.x * blockDim.x + threadIdx.x;
    if (i < NE) {
        int s, d;
        if (g_is64) {
            const long long* p = (const long long*)ei;
            s = (int)p[i]; d = (int)p[NE + i];
        } else {
            const int* p = (const int*)ei;
            s = p[i]; d = p[NE + i];
        }
        g_src[i] = s;
        g_dst[i] = d;
        atomicAdd(&g_icnt[d], 1);
    }
    const float4* x4 = (const float4*)x;
    const int total = gridDim.x * blockDim.x;
    for (int q = i; q < NN * 32; q += total) {
        float4 v = x4[q];
        __half2* dsth = (__half2*)(g_xh + (size_t)q * 4);
        dsth[0] = __floats2half2_rn(v.x, v.y);
        dsth[1] = __floats2half2_rn(v.z, v.w);
    }
}

// ---------------- CSR build ----------------
__global__ void scan1() {
    __shared__ int sh[256];
    int i = blockIdx.x * 256 + threadIdx.x;
    sh[threadIdx.x] = (i < NN) ? g_icnt[i] : 0;
    for (int o = 128; o > 0; o >>= 1) {
        __syncthreads();
        if (threadIdx.x < o) sh[threadIdx.x] += sh[threadIdx.x + o];
    }
    if (threadIdx.x == 0) g_bsum[blockIdx.x] = sh[0];
}

__global__ void scan23() {
    __shared__ int sb[512];
    __shared__ int sh[256];
    int t = threadIdx.x;
    sb[t] = (t < 391) ? g_bsum[t] : 0;
    __syncthreads();
    #pragma unroll
    for (int o = 1; o < 512; o <<= 1) {
        int v = (t >= o) ? sb[t - o] : 0;
        __syncthreads();
        sb[t] += v;
        __syncthreads();
    }
    int blockoff = blockIdx.x ? sb[blockIdx.x - 1] : 0;

    int i = blockIdx.x * 256 + t;
    int v = 0;
    if (t < 256) {
        v = (i < NN) ? g_icnt[i] : 0;
        sh[t] = v;
    }
    __syncthreads();
    #pragma unroll
    for (int o = 1; o < 256; o <<= 1) {
        int u = (t < 256 && t >= o) ? sh[t - o] : 0;
        __syncthreads();
        if (t < 256) sh[t] += u;
        __syncthreads();
    }
    if (t < 256 && i < NN) {
        int excl = blockoff + sh[t] - v;
        g_rowptr[i] = excl;
        g_cursor[i] = excl;
        g_inv[i] = 1.0f / fmaxf((float)v, 1.0f);
    }
}

__global__ void fill_kernel() {
    int i = blockIdx.x * blockDim.x + threadIdx.x;
    if (i >= NE) return;
    int slot = atomicAdd(&g_cursor[g_dst[i]], 1);
    g_adj[slot] = g_src[i];
}

// ---------------- gather layer 1: warp per node, fp16 in, fp16 mean out ----------------
__global__ void __launch_bounds__(256) gather1_kernel() {
    int node = (blockIdx.x * blockDim.x + threadIdx.x) >> 5;
    int lane = threadIdx.x & 31;
    if (node >= NN) return;
    int beg = g_rowptr[node];
    int end = beg + g_icnt[node];
    const uint2* xh = (const uint2*)g_xh;
    float4 acc = {0.f, 0.f, 0.f, 0.f};
    int j = beg;
    for (; j + 4 <= end; j += 4) {
        int s0 = __ldg(&g_adj[j]);
        int s1 = __ldg(&g_adj[j + 1]);
        int s2 = __ldg(&g_adj[j + 2]);
        int s3 = __ldg(&g_adj[j + 3]);
        uint2 u0 = xh[(size_t)s0 * 32 + lane];
        uint2 u1 = xh[(size_t)s1 * 32 + lane];
        uint2 u2 = xh[(size_t)s2 * 32 + lane];
        uint2 u3 = xh[(size_t)s3 * 32 + lane];
        #pragma unroll
        for (int q = 0; q < 4; q++) {
            uint2 u = (q == 0) ? u0 : (q == 1) ? u1 : (q == 2) ? u2 : u3;
            float2 fa = __half22float2(*(__half2*)&u.x);
            float2 fb = __half22float2(*(__half2*)&u.y);
            acc.x += fa.x; acc.y += fa.y; acc.z += fb.x; acc.w += fb.y;
        }
    }
    for (; j < end; j++) {
        int s = __ldg(&g_adj[j]);
        uint2 u = xh[(size_t)s * 32 + lane];
        float2 fa = __half22float2(*(__half2*)&u.x);
        float2 fb = __half22float2(*(__half2*)&u.y);
        acc.x += fa.x; acc.y += fa.y; acc.z += fb.x; acc.w += fb.y;
    }
    float iv = g_inv[node];
    uint2 o;
    *(__half2*)&o.x = __floats2half2_rn(acc.x * iv, acc.y * iv);
    *(__half2*)&o.y = __floats2half2_rn(acc.z * iv, acc.w * iv);
    ((uint2*)g_meanh)[(size_t)node * 32 + lane] = o;
}

// ---------------- gather layer 2 + epilogue (fp16 t2, MLP-8) ----------------
__global__ void __launch_bounds__(320) gather2_kernel(const float* __restrict__ b2,
                                                      float* __restrict__ out) {
    int i = blockIdx.x * blockDim.x + threadIdx.x;
    if (i >= NN * 10) return;
    int node = i / 10;
    int c = i - node * 10;
    int beg = g_rowptr[node];
    int end = beg + g_icnt[node];
    const uint2* t2h = (const uint2*)g_t2h;
    float4 acc = {0.f, 0.f, 0.f, 0.f};
    int j = beg;
    for (; j + 8 <= end; j += 8) {
        int s[8];
        #pragma unroll
        for (int q = 0; q < 8; q++) s[q] = __ldg(&g_adj[j + q]);
        uint2 v[8];
        #pragma unroll
        for (int q = 0; q < 8; q++) v[q] = t2h[(size_t)s[q] * 10 + c];
        #pragma unroll
        for (int q = 0; q < 8; q++) {
            float2 fa = __half22float2(*(__half2*)&v[q].x);
            float2 fb = __half22float2(*(__half2*)&v[q].y);
            acc.x += fa.x; acc.y += fa.y; acc.z += fb.x; acc.w += fb.y;
        }
    }
    if (j + 4 <= end) {
        int s[4];
        #pragma unroll
        for (int q = 0; q < 4; q++) s[q] = __ldg(&g_adj[j + q]);
        uint2 v[4];
        #pragma unroll
        for (int q = 0; q < 4; q++) v[q] = t2h[(size_t)s[q] * 10 + c];
        #pragma unroll
        for (int q = 0; q < 4; q++) {
            float2 fa = __half22float2(*(__half2*)&v[q].x);
            float2 fb = __half22float2(*(__half2*)&v[q].y);
            acc.x += fa.x; acc.y += fa.y; acc.z += fb.x; acc.w += fb.y;
        }
        j += 4;
    }
    for (; j < end; j++) {
        int s = __ldg(&g_adj[j]);
        uint2 u = t2h[(size_t)s * 10 + c];
        float2 fa = __half22float2(*(__half2*)&u.x);
        float2 fb = __half22float2(*(__half2*)&u.y);
        acc.x += fa.x; acc.y += fa.y; acc.z += fb.x; acc.w += fb.y;
    }
    float iv = g_inv[node];
    float4 r = ((const float4*)g_r2)[i];
    float4 b = ((const float4*)b2)[c];
    float4 o;
    o.x = acc.x * iv + r.x + b.x;
    o.y = acc.y * iv + r.y + b.y;
    o.z = acc.z * iv + r.z + b.z;
    o.w = acc.w * iv + r.w + b.w;
    ((float4*)out)[i] = o;
}

// ---------------- fused GEMM, fp16 mma (m16n8k16) ----------------
// smem (halves): sA 2x128x40 | sB 2x128x40 | sH 128x136 | sW2 80x136 | bias 128 fp32
#define SM_A  0
#define SM_B  10240
#define SM_H  20480
#define SM_W2 37888
#define SM_BIH 48768
#define GF_SMEM (48768 * 2 + 512)
__global__ void __launch_bounds__(256) gemm_fused(const float* __restrict__ bias) {
    extern __shared__ __half sm16[];
    __half* sA = sm16 + SM_A;
    __half* sB = sm16 + SM_B;
    __half* sH = sm16 + SM_H;
    __half* sW2 = sm16 + SM_W2;
    float* sBias = (float*)(sm16 + SM_BIH);

    const int tid = threadIdx.x, lane = tid & 31, wid = tid >> 5;
    const int wm = wid & 3, wn = wid >> 2;
    const int row0 = blockIdx.x * 128;
    if (tid < 128) sBias[tid] = bias[tid];

    {   // stage W2 [80][128] fp16 -> sW2 [80][LKH] (1280 x 16B)
        #pragma unroll
        for (int t = 0; t < 5; t++) {
            int i = tid + t * 256;
            int n = i >> 4, seg = i & 15;
            cp16((uint32_t)__cvta_generic_to_shared(sW2 + n * LKH + seg * 8),
                 g_W2h + n * 128 + seg * 8);
        }
    }

    float acc[2][8][4];
    #pragma unroll
    for (int mt = 0; mt < 2; mt++)
        #pragma unroll
        for (int nt = 0; nt < 8; nt++)
            #pragma unroll
            for (int q = 0; q < 4; q++) acc[mt][nt][q] = 0.f;

    auto issue = [&](int c) {
        const __half* asrc = (c < 4) ? g_meanh : g_xh;
        const int k0 = (c & 3) * 32;
        __half* dA = sA + (c & 1) * (128 * LKA);
        __half* dB = sB + (c & 1) * (128 * LKA);
        // 512 x 16B per tile pair: 2 per thread each
        #pragma unroll
        for (int t = 0; t < 2; t++) {
            int i = tid + t * 256;
            int r = i >> 2, seg = i & 3;        // r 0..127, seg 0..3 (8 halves each)
            int grow = row0 + r;
            if (grow > NN - 1) grow = NN - 1;
            cp16((uint32_t)__cvta_generic_to_shared(dA + r * LKA + seg * 8),
                 asrc + (size_t)grow * 128 + k0 + seg * 8);
            cp16((uint32_t)__cvta_generic_to_shared(dB + r * LKA + seg * 8),
                 g_W1h + r * 256 + c * 32 + seg * 8);
        }
        asm volatile("cp.async.commit_group;" ::: "memory");
    };

    issue(0);
    for (int c = 0; c < 8; c++) {
        if (c < 7) {
            issue(c + 1);
            asm volatile("cp.async.wait_group 1;" ::: "memory");
        } else {
            asm volatile("cp.async.wait_group 0;" ::: "memory");
        }
        __syncthreads();
        const __half* A = sA + (c & 1) * (128 * LKA);
        const __half* B = sB + (c & 1) * (128 * LKA);
        #pragma unroll
        for (int ks = 0; ks < 2; ks++) {
            const int bk = ks * 16 + (lane & 3) * 2;
            uint32_t b0[8], b1[8];
            #pragma unroll
            for (int nt = 0; nt < 8; nt++) {
                int n = wn * 64 + nt * 8 + (lane >> 2);
                b0[nt] = *(const uint32_t*)(B + n * LKA + bk);
                b1[nt] = *(const uint32_t*)(B + n * LKA + bk + 8);
            }
            #pragma unroll
            for (int mt = 0; mt < 2; mt++) {
                int r = wm * 32 + mt * 16 + (lane >> 2);
                uint32_t a0 = *(const uint32_t*)(A + r * LKA + bk);
                uint32_t a1 = *(const uint32_t*)(A + (r + 8) * LKA + bk);
                uint32_t a2 = *(const uint32_t*)(A + r * LKA + bk + 8);
                uint32_t a3 = *(const uint32_t*)(A + (r + 8) * LKA + bk + 8);
                #pragma unroll
                for (int nt = 0; nt < 8; nt++)
                    mma16(acc[mt][nt], a0, a1, a2, a3, b0[nt], b1[nt]);
            }
        }
        __syncthreads();
    }

    // phase A epilogue: bias+relu -> sH (fp16)
    #pragma unroll
    for (int mt = 0; mt < 2; mt++) {
        int r = wm * 32 + mt * 16 + (lane >> 2);
        #pragma unroll
        for (int nt = 0; nt < 8; nt++) {
            int cb = wn * 64 + nt * 8 + 2 * (lane & 3);
            float h00 = fmaxf(acc[mt][nt][0] + sBias[cb], 0.f);
            float h01 = fmaxf(acc[mt][nt][1] + sBias[cb + 1], 0.f);
            float h10 = fmaxf(acc[mt][nt][2] + sBias[cb], 0.f);
            float h11 = fmaxf(acc[mt][nt][3] + sBias[cb + 1], 0.f);
            *(__half2*)(sH + r * LKH + cb)       = __floats2half2_rn(h00, h01);
            *(__half2*)(sH + (r + 8) * LKH + cb) = __floats2half2_rn(h10, h11);
        }
    }
    __syncthreads();

    // phase B: [t2|r2] = h @ W2cat (K=128 fp16 from smem)
    float acc2[10][4];
    #pragma unroll
    for (int nt = 0; nt < 10; nt++)
        #pragma unroll
        for (int q = 0; q < 4; q++) acc2[nt][q] = 0.f;

    const int r = wid * 16 + (lane >> 2);
    #pragma unroll
    for (int ks = 0; ks < 8; ks++) {
        const int bk = ks * 16 + (lane & 3) * 2;
        uint32_t a0 = *(const uint32_t*)(sH + r * LKH + bk);
        uint32_t a1 = *(const uint32_t*)(sH + (r + 8) * LKH + bk);
        uint32_t a2 = *(const uint32_t*)(sH + r * LKH + bk + 8);
        uint32_t a3 = *(const uint32_t*)(sH + (r + 8) * LKH + bk + 8);
        #pragma unroll
        for (int nt = 0; nt < 10; nt++) {
            int n = nt * 8 + (lane >> 2);
            uint32_t b0 = *(const uint32_t*)(sW2 + n * LKH + bk);
            uint32_t b1 = *(const uint32_t*)(sW2 + n * LKH + bk + 8);
            mma16(acc2[nt], a0, a1, a2, a3, b0, b1);
        }
    }

    int gr = row0 + r;
    #pragma unroll
    for (int nt = 0; nt < 10; nt++) {
        int cb = nt * 8 + 2 * (lane & 3);
        if (cb < 40) {
            if (gr < NN)
                *(__half2*)(g_t2h + (size_t)gr * 40 + cb) =
                    __floats2half2_rn(acc2[nt][0], acc2[nt][1]);
            if (gr + 8 < NN)
                *(__half2*)(g_t2h + (size_t)(gr + 8) * 40 + cb) =
                    __floats2half2_rn(acc2[nt][2], acc2[nt][3]);
        } else {
            int cr = cb - 40;
            if (gr < NN)
                *(float2*)(g_r2 + (size_t)gr * 40 + cr) =
                    make_float2(acc2[nt][0], acc2[nt][1]);
            if (gr + 8 < NN)
                *(float2*)(g_r2 + (size_t)(gr + 8) * 40 + cr) =
                    make_float2(acc2[nt][2], acc2[nt][3]);
        }
    }
}

// ---------------- launcher ----------------
extern "C" void kernel_launch(void* const* d_in, const int* in_sizes, int n_in,
                              void* d_out, int out_size) {
    const float* x    = (const float*)d_in[0];
    const void*  edge = d_in[1];
    const float* W1l  = (const float*)d_in[2];
    const float* W1r  = (const float*)d_in[3];
    const float* b1   = (const float*)d_in[4];
    const float* W2l  = (const float*)d_in[5];
    const float* W2r  = (const float*)d_in[6];
    const float* b2   = (const float*)d_in[7];
    float* out = (float*)d_out;

    static int once = 0;
    if (!once) {
        cudaFuncSetAttribute(gemm_fused, cudaFuncAttributeMaxDynamicSharedMemorySize, GF_SMEM);
        once = 1;
    }

    const int NBLK = (NN + 255) / 256;       // 391

    init_kernel<<<NBLK, 256>>>((const unsigned int*)edge, W1l, W1r, W2l, W2r);
    convert_kernel<<<(NE + 255) / 256, 256>>>(edge, x);
    scan1<<<NBLK, 256>>>();
    scan23<<<NBLK, 512>>>();
    fill_kernel<<<(NE + 255) / 256, 256>>>();
    gather1_kernel<<<(NN * 32 + 255) / 256, 256>>>();
    gemm_fused<<<(NN + 127) / 128, 256, GF_SMEM>>>(b1);
    gather2_kernel<<<(NN * 10 + 319) / 320, 320>>>(b2, out);
}

// round 14
// speedup vs baseline: 1.4991x; 1.0621x over previous
#include <cuda_runtime.h>
#include <cuda_fp16.h>
#include <cstdint>

#define NN 100000
#define NE 800000
#define LKA 40    // halves per row: A/B K-chunk tiles (32 + 8 pad)
#define LKH 136   // halves per row: sH / sW2 (128 + 8 pad)

// ---------------- device scratch ----------------
__device__ __half g_meanh[(size_t)NN * 128]; // mean-aggregated x (fp16)
__device__ __half g_xh [(size_t)NN * 128];   // fp16 cache of x
__device__ __half g_t2h[(size_t)NN * 40];    // h @ W2l (fp16)
__device__ float  g_r2 [(size_t)NN * 40];    // h @ W2r (fp32)
__device__ int    g_icnt[NN];
__device__ float  g_inv [NN];
__device__ int    g_rowptr[NN];
__device__ int    g_cursor[NN];
__device__ int    g_adj [NE];
__device__ int    g_src [NE];
__device__ int    g_dst [NE];
__device__ int    g_total;
__device__ int    g_is64;
__device__ __half g_W1h[128 * 256];   // B layer1: [n=128][k=256] fp16
__device__ __half g_W2h[80 * 128];    // B layer2: [n=80][k=128] fp16

// ---------------- helpers ----------------
__device__ __forceinline__ void cp16(uint32_t dst, const void* src) {
    asm volatile("cp.async.cg.shared.global [%0], [%1], 16;" :: "r"(dst), "l"(src));
}
__device__ __forceinline__ void mma16(float* c, uint32_t a0, uint32_t a1,
                                      uint32_t a2, uint32_t a3,
                                      uint32_t b0, uint32_t b1) {
    asm volatile("mma.sync.aligned.m16n8k16.row.col.f32.f16.f16.f32 "
        "{%0,%1,%2,%3}, {%4,%5,%6,%7}, {%8,%9}, {%0,%1,%2,%3};"
        : "+f"(c[0]), "+f"(c[1]), "+f"(c[2]), "+f"(c[3])
        : "r"(a0), "r"(a1), "r"(a2), "r"(a3), "r"(b0), "r"(b1));
}

// ---------------- init: zero icnt + total; detect dtype; prep fp16 weights ----------------
__global__ void init_kernel(const unsigned int* __restrict__ w,
                            const float* __restrict__ W1l, const float* __restrict__ W1r,
                            const float* __restrict__ W2l, const float* __restrict__ W2r) {
    int i = blockIdx.x * blockDim.x + threadIdx.x;
    if (i < NN) g_icnt[i] = 0;
    if (i == 0) g_total = 0;
    if (blockIdx.x == 0) {
        int nz = 0;
        for (int t = threadIdx.x; t < 2048; t += blockDim.x)
            nz |= (w[2 * t + 1] != 0u);
        nz = __syncthreads_or(nz);
        if (threadIdx.x == 0) g_is64 = (nz == 0) ? 1 : 0;
    }
    if (i < 32768) {
        int k = i >> 7, n = i & 127;
        float v = (k < 128) ? W1l[k * 128 + n] : W1r[(k - 128) * 128 + n];
        g_W1h[n * 256 + k] = __float2half_rn(v);
    } else if (i < 32768 + 10240) {
        int u = i - 32768;
        int k = u / 80, n = u - k * 80;
        float v = (n < 40) ? W2l[k * 40 + n] : W2r[k * 40 + (n - 40)];
        g_W2h[n * 128 + k] = __float2half_rn(v);
    }
}

// ---------------- convert: edges -> src/dst + degrees ----------------
__global__ void convert_kernel(const void* __restrict__ ei) {
    int i = blockIdx.x * blockDim.x + threadIdx.x;
    if (i >= NE) return;
    int s, d;
    if (g_is64) {
        const long long* p = (const long long*)ei;
        s = (int)p[i]; d = (int)p[NE + i];
    } else {
        const int* p = (const int*)ei;
        s = p[i]; d = p[NE + i];
    }
    g_src[i] = s;
    g_dst[i] = d;
    atomicAdd(&g_icnt[d], 1);
}

// ---------------- single-kernel scan: block-local scan + atomic base allocation ----------------
// Block ranges land in arbitrary global order — CSR stays valid (disjoint, sized icnt).
__global__ void scan_kernel() {              // 391 x 256
    __shared__ int sh[256];
    __shared__ int sbase;
    int t = threadIdx.x;
    int i = blockIdx.x * 256 + t;
    int v = (i < NN) ? g_icnt[i] : 0;
    sh[t] = v;
    __syncthreads();
    #pragma unroll
    for (int o = 1; o < 256; o <<= 1) {
        int u = (t >= o) ? sh[t - o] : 0;
        __syncthreads();
        sh[t] += u;
        __syncthreads();
    }
    if (t == 255) sbase = atomicAdd(&g_total, sh[255]);
    __syncthreads();
    if (i < NN) {
        int excl = sbase + sh[t] - v;
        g_rowptr[i] = excl;
        g_cursor[i] = excl;
        g_inv[i] = 1.0f / fmaxf((float)v, 1.0f);
    }
}

// ---------------- fill adjacency + x -> fp16 (overlaps atomics with streaming) ----------------
__global__ void fill_kernel(const float* __restrict__ x) {
    int i = blockIdx.x * blockDim.x + threadIdx.x;
    if (i < NE) {
        int slot = atomicAdd(&g_cursor[g_dst[i]], 1);
        g_adj[slot] = g_src[i];
    }
    const float4* x4 = (const float4*)x;
    const int total = gridDim.x * blockDim.x;
    for (int q = i; q < NN * 32; q += total) {
        float4 v = x4[q];
        __half2* dsth = (__half2*)(g_xh + (size_t)q * 4);
        dsth[0] = __floats2half2_rn(v.x, v.y);
        dsth[1] = __floats2half2_rn(v.z, v.w);
    }
}

// ---------------- gather layer 1: warp per node, fp16, MLP-8 ----------------
__global__ void __launch_bounds__(256) gather1_kernel() {
    int node = (blockIdx.x * blockDim.x + threadIdx.x) >> 5;
    int lane = threadIdx.x & 31;
    if (node >= NN) return;
    int beg = g_rowptr[node];
    int end = beg + g_icnt[node];
    const uint2* xh = (const uint2*)g_xh;
    float4 acc = {0.f, 0.f, 0.f, 0.f};
    int j = beg;
    for (; j + 8 <= end; j += 8) {
        int s[8];
        #pragma unroll
        for (int q = 0; q < 8; q++) s[q] = __ldg(&g_adj[j + q]);
        uint2 u[8];
        #pragma unroll
        for (int q = 0; q < 8; q++) u[q] = xh[(size_t)s[q] * 32 + lane];
        #pragma unroll
        for (int q = 0; q < 8; q++) {
            float2 fa = __half22float2(*(__half2*)&u[q].x);
            float2 fb = __half22float2(*(__half2*)&u[q].y);
            acc.x += fa.x; acc.y += fa.y; acc.z += fb.x; acc.w += fb.y;
        }
    }
    if (j + 4 <= end) {
        int s[4];
        #pragma unroll
        for (int q = 0; q < 4; q++) s[q] = __ldg(&g_adj[j + q]);
        uint2 u[4];
        #pragma unroll
        for (int q = 0; q < 4; q++) u[q] = xh[(size_t)s[q] * 32 + lane];
        #pragma unroll
        for (int q = 0; q < 4; q++) {
            float2 fa = __half22float2(*(__half2*)&u[q].x);
            float2 fb = __half22float2(*(__half2*)&u[q].y);
            acc.x += fa.x; acc.y += fa.y; acc.z += fb.x; acc.w += fb.y;
        }
        j += 4;
    }
    for (; j < end; j++) {
        int s = __ldg(&g_adj[j]);
        uint2 u = xh[(size_t)s * 32 + lane];
        float2 fa = __half22float2(*(__half2*)&u.x);
        float2 fb = __half22float2(*(__half2*)&u.y);
        acc.x += fa.x; acc.y += fa.y; acc.z += fb.x; acc.w += fb.y;
    }
    float iv = g_inv[node];
    uint2 o;
    *(__half2*)&o.x = __floats2half2_rn(acc.x * iv, acc.y * iv);
    *(__half2*)&o.y = __floats2half2_rn(acc.z * iv, acc.w * iv);
    ((uint2*)g_meanh)[(size_t)node * 32 + lane] = o;
}

// ---------------- gather layer 2 + epilogue (fp16 t2, MLP-8) ----------------
__global__ void __launch_bounds__(320) gather2_kernel(const float* __restrict__ b2,
                                                      float* __restrict__ out) {
    int i = blockIdx.x * blockDim.x + threadIdx.x;
    if (i >= NN * 10) return;
    int node = i / 10;
    int c = i - node * 10;
    int beg = g_rowptr[node];
    int end = beg + g_icnt[node];
    const uint2* t2h = (const uint2*)g_t2h;
    float4 acc = {0.f, 0.f, 0.f, 0.f};
    int j = beg;
    for (; j + 8 <= end; j += 8) {
        int s[8];
        #pragma unroll
        for (int q = 0; q < 8; q++) s[q] = __ldg(&g_adj[j + q]);
        uint2 v[8];
        #pragma unroll
        for (int q = 0; q < 8; q++) v[q] = t2h[(size_t)s[q] * 10 + c];
        #pragma unroll
        for (int q = 0; q < 8; q++) {
            float2 fa = __half22float2(*(__half2*)&v[q].x);
            float2 fb = __half22float2(*(__half2*)&v[q].y);
            acc.x += fa.x; acc.y += fa.y; acc.z += fb.x; acc.w += fb.y;
        }
    }
    if (j + 4 <= end) {
        int s[4];
        #pragma unroll
        for (int q = 0; q < 4; q++) s[q] = __ldg(&g_adj[j + q]);
        uint2 v[4];
        #pragma unroll
        for (int q = 0; q < 4; q++) v[q] = t2h[(size_t)s[q] * 10 + c];
        #pragma unroll
        for (int q = 0; q < 4; q++) {
            float2 fa = __half22float2(*(__half2*)&v[q].x);
            float2 fb = __half22float2(*(__half2*)&v[q].y);
            acc.x += fa.x; acc.y += fa.y; acc.z += fb.x; acc.w += fb.y;
        }
        j += 4;
    }
    for (; j < end; j++) {
        int s = __ldg(&g_adj[j]);
        uint2 u = t2h[(size_t)s * 10 + c];
        float2 fa = __half22float2(*(__half2*)&u.x);
        float2 fb = __half22float2(*(__half2*)&u.y);
        acc.x += fa.x; acc.y += fa.y; acc.z += fb.x; acc.w += fb.y;
    }
    float iv = g_inv[node];
    float4 r = ((const float4*)g_r2)[i];
    float4 b = ((const float4*)b2)[c];
    float4 o;
    o.x = acc.x * iv + r.x + b.x;
    o.y = acc.y * iv + r.y + b.y;
    o.z = acc.z * iv + r.z + b.z;
    o.w = acc.w * iv + r.w + b.w;
    ((float4*)out)[i] = o;
}

// ---------------- fused GEMM, fp16 mma (m16n8k16) — byte-identical to R13 ----------------
#define SM_A  0
#define SM_B  10240
#define SM_H  20480
#define SM_W2 37888
#define SM_BIH 48768
#define GF_SMEM (48768 * 2 + 512)
__global__ void __launch_bounds__(256) gemm_fused(const float* __restrict__ bias) {
    extern __shared__ __half sm16[];
    __half* sA = sm16 + SM_A;
    __half* sB = sm16 + SM_B;
    __half* sH = sm16 + SM_H;
    __half* sW2 = sm16 + SM_W2;
    float* sBias = (float*)(sm16 + SM_BIH);

    const int tid = threadIdx.x, lane = tid & 31, wid = tid >> 5;
    const int wm = wid & 3, wn = wid >> 2;
    const int row0 = blockIdx.x * 128;
    if (tid < 128) sBias[tid] = bias[tid];

    {   // stage W2 [80][128] fp16 -> sW2 [80][LKH]
        #pragma unroll
        for (int t = 0; t < 5; t++) {
            int i = tid + t * 256;
            int n = i >> 4, seg = i & 15;
            cp16((uint32_t)__cvta_generic_to_shared(sW2 + n * LKH + seg * 8),
                 g_W2h + n * 128 + seg * 8);
        }
    }

    float acc[2][8][4];
    #pragma unroll
    for (int mt = 0; mt < 2; mt++)
        #pragma unroll
        for (int nt = 0; nt < 8; nt++)
            #pragma unroll
            for (int q = 0; q < 4; q++) acc[mt][nt][q] = 0.f;

    auto issue = [&](int c) {
        const __half* asrc = (c < 4) ? g_meanh : g_xh;
        const int k0 = (c & 3) * 32;
        __half* dA = sA + (c & 1) * (128 * LKA);
        __half* dB = sB + (c & 1) * (128 * LKA);
        #pragma unroll
        for (int t = 0; t < 2; t++) {
            int i = tid + t * 256;
            int r = i >> 2, seg = i & 3;
            int grow = row0 + r;
            if (grow > NN - 1) grow = NN - 1;
            cp16((uint32_t)__cvta_generic_to_shared(dA + r * LKA + seg * 8),
                 asrc + (size_t)grow * 128 + k0 + seg * 8);
            cp16((uint32_t)__cvta_generic_to_shared(dB + r * LKA + seg * 8),
                 g_W1h + r * 256 + c * 32 + seg * 8);
        }
        asm volatile("cp.async.commit_group;" ::: "memory");
    };

    issue(0);
    for (int c = 0; c < 8; c++) {
        if (c < 7) {
            issue(c + 1);
            asm volatile("cp.async.wait_group 1;" ::: "memory");
        } else {
            asm volatile("cp.async.wait_group 0;" ::: "memory");
        }
        __syncthreads();
        const __half* A = sA + (c & 1) * (128 * LKA);
        const __half* B = sB + (c & 1) * (128 * LKA);
        #pragma unroll
        for (int ks = 0; ks < 2; ks++) {
            const int bk = ks * 16 + (lane & 3) * 2;
            uint32_t b0[8], b1[8];
            #pragma unroll
            for (int nt = 0; nt < 8; nt++) {
                int n = wn * 64 + nt * 8 + (lane >> 2);
                b0[nt] = *(const uint32_t*)(B + n * LKA + bk);
                b1[nt] = *(const uint32_t*)(B + n * LKA + bk + 8);
            }
            #pragma unroll
            for (int mt = 0; mt < 2; mt++) {
                int r = wm * 32 + mt * 16 + (lane >> 2);
                uint32_t a0 = *(const uint32_t*)(A + r * LKA + bk);
                uint32_t a1 = *(const uint32_t*)(A + (r + 8) * LKA + bk);
                uint32_t a2 = *(const uint32_t*)(A + r * LKA + bk + 8);
                uint32_t a3 = *(const uint32_t*)(A + (r + 8) * LKA + bk + 8);
                #pragma unroll
                for (int nt = 0; nt < 8; nt++)
                    mma16(acc[mt][nt], a0, a1, a2, a3, b0[nt], b1[nt]);
            }
        }
        __syncthreads();
    }

    // phase A epilogue: bias+relu -> sH (fp16)
    #pragma unroll
    for (int mt = 0; mt < 2; mt++) {
        int r = wm * 32 + mt * 16 + (lane >> 2);
        #pragma unroll
        for (int nt = 0; nt < 8; nt++) {
            int cb = wn * 64 + nt * 8 + 2 * (lane & 3);
            float h00 = fmaxf(acc[mt][nt][0] + sBias[cb], 0.f);
            float h01 = fmaxf(acc[mt][nt][1] + sBias[cb + 1], 0.f);
            float h10 = fmaxf(acc[mt][nt][2] + sBias[cb], 0.f);
            float h11 = fmaxf(acc[mt][nt][3] + sBias[cb + 1], 0.f);
            *(__half2*)(sH + r * LKH + cb)       = __floats2half2_rn(h00, h01);
            *(__half2*)(sH + (r + 8) * LKH + cb) = __floats2half2_rn(h10, h11);
        }
    }
    __syncthreads();

    // phase B: [t2|r2] = h @ W2cat
    float acc2[10][4];
    #pragma unroll
    for (int nt = 0; nt < 10; nt++)
        #pragma unroll
        for (int q = 0; q < 4; q++) acc2[nt][q] = 0.f;

    const int r = wid * 16 + (lane >> 2);
    #pragma unroll
    for (int ks = 0; ks < 8; ks++) {
        const int bk = ks * 16 + (lane & 3) * 2;
        uint32_t a0 = *(const uint32_t*)(sH + r * LKH + bk);
        uint32_t a1 = *(const uint32_t*)(sH + (r + 8) * LKH + bk);
        uint32_t a2 = *(const uint32_t*)(sH + r * LKH + bk + 8);
        uint32_t a3 = *(const uint32_t*)(sH + (r + 8) * LKH + bk + 8);
        #pragma unroll
        for (int nt = 0; nt < 10; nt++) {
            int n = nt * 8 + (lane >> 2);
            uint32_t b0 = *(const uint32_t*)(sW2 + n * LKH + bk);
            uint32_t b1 = *(const uint32_t*)(sW2 + n * LKH + bk + 8);
            mma16(acc2[nt], a0, a1, a2, a3, b0, b1);
        }
    }

    int gr = row0 + r;
    #pragma unroll
    for (int nt = 0; nt < 10; nt++) {
        int cb = nt * 8 + 2 * (lane & 3);
        if (cb < 40) {
            if (gr < NN)
                *(__half2*)(g_t2h + (size_t)gr * 40 + cb) =
                    __floats2half2_rn(acc2[nt][0], acc2[nt][1]);
            if (gr + 8 < NN)
                *(__half2*)(g_t2h + (size_t)(gr + 8) * 40 + cb) =
                    __floats2half2_rn(acc2[nt][2], acc2[nt][3]);
        } else {
            int cr = cb - 40;
            if (gr < NN)
                *(float2*)(g_r2 + (size_t)gr * 40 + cr) =
                    make_float2(acc2[nt][0], acc2[nt][1]);
            if (gr + 8 < NN)
                *(float2*)(g_r2 + (size_t)(gr + 8) * 40 + cr) =
                    make_float2(acc2[nt][2], acc2[nt][3]);
        }
    }
}

// ---------------- launcher ----------------
extern "C" void kernel_launch(void* const* d_in, const int* in_sizes, int n_in,
                              void* d_out, int out_size) {
    const float* x    = (const float*)d_in[0];
    const void*  edge = d_in[1];
    const float* W1l  = (const float*)d_in[2];
    const float* W1r  = (const float*)d_in[3];
    const float* b1   = (const float*)d_in[4];
    const float* W2l  = (const float*)d_in[5];
    const float* W2r  = (const float*)d_in[6];
    const float* b2   = (const float*)d_in[7];
    float* out = (float*)d_out;

    static int once = 0;
    if (!once) {
        cudaFuncSetAttribute(gemm_fused, cudaFuncAttributeMaxDynamicSharedMemorySize, GF_SMEM);
        once = 1;
    }

    const int NBLK = (NN + 255) / 256;       // 391

    init_kernel<<<NBLK, 256>>>((const unsigned int*)edge, W1l, W1r, W2l, W2r);
    convert_kernel<<<(NE + 255) / 256, 256>>>(edge);
    scan_kernel<<<NBLK, 256>>>();
    fill_kernel<<<(NE + 255) / 256, 256>>>(x);
    gather1_kernel<<<(NN * 32 + 255) / 256, 256>>>();
    gemm_fused<<<(NN + 127) / 128, 256, GF_SMEM>>>(b1);
    gather2_kernel<<<(NN * 10 + 319) / 320, 320>>>(b2, out);
}